// round 6
// baseline (speedup 1.0000x reference)
#include <cuda_runtime.h>
#include <cuda_bf16.h>
#include <math.h>
#include <stdint.h>

// ============================================================================
// MultiSizeProjHead via portable mma.sync (bf16 split, fp32 accum)
// Round 6: 256x128 tiles; head pairs two same-class samples per CTA (shared
// weight tile), separate zero-fill kernel, 6:1 MMA:LDSM ratio.
// ============================================================================
#define EMBED   1024
#define INTER   4096
#define SBASE   672
#define OUTD    21
#define NSAMP   256
#define PTOK    128
#define MROWS   (NSAMP * PTOK)
#define TTOT    2520        // 168 + 336 + 672 + 1344

#define KC       32                   // K per SMEM stage
#define TSTRIDE  80                   // bytes per smem row: 32 bf16 + 8 pad
#define TILE_A   (256 * TSTRIDE)      // 20480 B  (256 x 32 bf16 tile)
#define TILE_BT  (128 * TSTRIDE)      // 10240 B  (128 x 32 bf16 tile)
#define STAGE_B  (2 * TILE_A + 2 * TILE_BT)   // Ah, Al, Bh, Bl = 61440
#define SMEM_TOTAL (2 * STAGE_B)              // double buffered: 122880

#define MAXPAIRS 132

__device__ __constant__ int c_T[4]    = {168, 336, 672, 1344};
__device__ __constant__ int c_Toff[4] = {0, 168, 504, 1176};

// ---------------- device scratch (no runtime allocation allowed) -----------
__device__ __nv_bfloat16 g_xh [(size_t)MROWS * EMBED];
__device__ __nv_bfloat16 g_xl [(size_t)MROWS * EMBED];
__device__ __nv_bfloat16 g_wih[(size_t)INTER * EMBED];
__device__ __nv_bfloat16 g_wil[(size_t)INTER * EMBED];
__device__ __nv_bfloat16 g_xsh[(size_t)MROWS * INTER];
__device__ __nv_bfloat16 g_xsl[(size_t)MROWS * INTER];
__device__ __nv_bfloat16 g_w2h[(size_t)TTOT * INTER];   // t-major: [t][k]
__device__ __nv_bfloat16 g_w2l[(size_t)TTOT * INTER];
__device__ __nv_bfloat16 g_wrh[(size_t)TTOT * EMBED];
__device__ __nv_bfloat16 g_wrl[(size_t)TTOT * EMBED];
__device__ float g_b2[TTOT];
__device__ float g_br[TTOT];
__device__ int g_pairA[MAXPAIRS];
__device__ int g_pairB[MAXPAIRS];
__device__ int g_pairCls[MAXPAIRS];

// ---------------- portable PTX helpers -------------------------------------
__device__ __forceinline__ uint32_t smem_to_u32(const void* p) {
    uint32_t a;
    asm("{ .reg .u64 t; cvta.to.shared.u64 t, %1; cvt.u32.u64 %0, t; }" : "=r"(a) : "l"(p));
    return a;
}
__device__ __forceinline__ void cp_async16(uint32_t dst, const void* src, uint32_t src_bytes) {
    asm volatile("cp.async.cg.shared.global [%0], [%1], 16, %2;"
                 :: "r"(dst), "l"(src), "r"(src_bytes) : "memory");
}
#define CP_COMMIT() asm volatile("cp.async.commit_group;" ::: "memory")
#define CP_WAIT0()  asm volatile("cp.async.wait_group 0;" ::: "memory")

__device__ __forceinline__ void ldsm_x4(uint32_t* r, uint32_t addr) {
    asm volatile("ldmatrix.sync.aligned.m8n8.x4.shared.b16 {%0,%1,%2,%3}, [%4];"
                 : "=r"(r[0]), "=r"(r[1]), "=r"(r[2]), "=r"(r[3]) : "r"(addr));
}
__device__ __forceinline__ void mma16816(float* c, const uint32_t* a, uint32_t b0, uint32_t b1) {
    asm volatile("mma.sync.aligned.m16n8k16.row.col.f32.bf16.bf16.f32 "
                 "{%0,%1,%2,%3}, {%4,%5,%6,%7}, {%8,%9}, {%0,%1,%2,%3};"
                 : "+f"(c[0]), "+f"(c[1]), "+f"(c[2]), "+f"(c[3])
                 : "r"(a[0]), "r"(a[1]), "r"(a[2]), "r"(a[3]), "r"(b0), "r"(b1));
}
__device__ __forceinline__ void split2(float v, __nv_bfloat16& h, __nv_bfloat16& l) {
    h = __float2bfloat16(v);
    l = __float2bfloat16(v - __bfloat162float(h));
}
__device__ __forceinline__ uint32_t pack2(__nv_bfloat16 a, __nv_bfloat16 b) {
    return (uint32_t)__bfloat16_as_ushort(a) | ((uint32_t)__bfloat16_as_ushort(b) << 16);
}

// ---- tile loaders (rows padded to 80B) -------------------------------------
// 256-row A tile, contiguous rows (GEMM1)
__device__ __forceinline__ void load_tileA(uint32_t sdst, const __nv_bfloat16* __restrict__ src,
                                           long row0, long stride, int k0, int tid) {
#pragma unroll
    for (int i = 0; i < 4; i++) {
        const int c = tid + (i << 8);          // 0..1023
        const int row = c >> 2, c4 = c & 3;
        cp_async16(sdst + (uint32_t)(row * TSTRIDE + c4 * 16),
                   src + (row0 + row) * stride + k0 + c4 * 8, 16u);
    }
}
// 256-row A tile from two samples (head): rows 0-127 -> r0a.., rows 128-255 -> r0b..
__device__ __forceinline__ void load_tileA_pair(uint32_t sdst, const __nv_bfloat16* __restrict__ src,
                                                long r0a, long r0b, long stride, int k0, int tid,
                                                bool bvalid) {
#pragma unroll
    for (int i = 0; i < 4; i++) {
        const int c = tid + (i << 8);
        const int row = c >> 2, c4 = c & 3;
        const bool lo = row < 128;
        const bool ok = lo || bvalid;
        const long grow = ok ? (lo ? r0a + row : r0b + (row - 128)) : r0a;
        cp_async16(sdst + (uint32_t)(row * TSTRIDE + c4 * 16),
                   src + grow * stride + k0 + c4 * 8, ok ? 16u : 0u);
    }
}
// 128-row B tile; rows >= vrows zero-filled
__device__ __forceinline__ void load_tileB(uint32_t sdst, const __nv_bfloat16* __restrict__ src,
                                           long row0, long stride, int k0, int tid, int vrows) {
#pragma unroll
    for (int i = 0; i < 2; i++) {
        const int c = tid + (i << 8);          // 0..511
        const int row = c >> 2, c4 = c & 3;
        const bool ok = (row < vrows);
        const long srow = ok ? (row0 + row) : row0;
        cp_async16(sdst + (uint32_t)(row * TSTRIDE + c4 * 16),
                   src + srow * stride + k0 + c4 * 8, ok ? 16u : 0u);
    }
}

// one KC=32 stage of split MMA on a 256x128 tile, warp tile 64x64.
// acc += Ah*Bh + Ah*Bl + Al*Bh
__device__ __forceinline__ void mma_stage(uint32_t base, int lane, int warp_m, int warp_n,
                                          float acc[4][8][4]) {
    const int lr = lane & 7, lg = lane >> 3;
    const int rowSel = ((lg & 1) << 3) + lr;
    const int colHalf = (lg >> 1) << 3;
#pragma unroll
    for (int k16 = 0; k16 < KC; k16 += 16) {
        const uint32_t colOff = (uint32_t)((k16 + colHalf) * 2);
        uint32_t bh[4][4], bl[4][4];
#pragma unroll
        for (int jj = 0; jj < 4; jj++) {
            const uint32_t addr = base + 2 * TILE_A +
                (uint32_t)((warp_n * 64 + jj * 16 + rowSel) * TSTRIDE) + colOff;
            ldsm_x4(bh[jj], addr);
            ldsm_x4(bl[jj], addr + TILE_BT);
        }
#pragma unroll
        for (int i = 0; i < 4; i++) {
            uint32_t ah[4], al[4];
            const uint32_t addr = base +
                (uint32_t)((warp_m * 64 + i * 16 + rowSel) * TSTRIDE) + colOff;
            ldsm_x4(ah, addr);
            ldsm_x4(al, addr + TILE_A);
#pragma unroll
            for (int j = 0; j < 8; j++) {
                const uint32_t b0h = bh[j >> 1][j & 1], b1h = bh[j >> 1][(j & 1) + 2];
                const uint32_t b0l = bl[j >> 1][j & 1], b1l = bl[j >> 1][(j & 1) + 2];
                mma16816(acc[i][j], ah, b0h, b1h);
                mma16816(acc[i][j], ah, b0l, b1l);
                mma16816(acc[i][j], al, b0h, b1h);
            }
        }
    }
}

// ---------------- prep kernel 1: split x, W_in into bf16 hi/lo -------------
__global__ void split_inputs_kernel(const float* __restrict__ x, const float* __restrict__ W_in) {
    const long nx = (long)MROWS * EMBED;
    const long nw = (long)INTER * EMBED;
    const long i = blockIdx.x * (long)blockDim.x + threadIdx.x;
    if (i >= nx + nw) return;
    float v; __nv_bfloat16 *ph, *pl; long j;
    if (i < nx) { j = i;      v = x[j];    ph = g_xh;  pl = g_xl;  }
    else        { j = i - nx; v = W_in[j]; ph = g_wih; pl = g_wil; }
    split2(v, ph[j], pl[j]);
}

// ---------------- prep kernel 2: interpolated head weights (t-major) -------
__device__ __forceinline__ void interp_coef(int tg, int& i0, int& i1, float& lam) {
    const int s = (tg < 168) ? 0 : (tg < 504) ? 1 : (tg < 1176) ? 2 : 3;
    const int t = tg - c_Toff[s];
    const float scale = (float)SBASE / (float)c_T[s];
    float src = fmaxf(((float)t + 0.5f) * scale - 0.5f, 0.0f);
    i0 = (int)src;
    if (i0 > SBASE - 1) i0 = SBASE - 1;
    i1 = min(i0 + 1, SBASE - 1);
    lam = src - (float)i0;
}

__global__ void build_weights_kernel(const float* __restrict__ Ws, const float* __restrict__ bs,
                                     const float* __restrict__ Wr, const float* __restrict__ brs) {
    const long n2 = (long)TTOT * INTER;
    const long nr = (long)TTOT * EMBED;
    const long total = n2 + nr + 2 * TTOT;
    const long i = blockIdx.x * (long)blockDim.x + threadIdx.x;
    if (i >= total) return;
    int i0, i1; float lam;
    if (i < n2) {
        const int t = (int)(i / INTER), k = (int)(i % INTER);
        interp_coef(t, i0, i1, lam);
        const float v = Ws[(long)i0 * INTER + k] * (1.0f - lam) + Ws[(long)i1 * INTER + k] * lam;
        split2(v, g_w2h[i], g_w2l[i]);
    } else if (i < n2 + nr) {
        const long j = i - n2;
        const int t = (int)(j / EMBED), k = (int)(j % EMBED);
        interp_coef(t, i0, i1, lam);
        const float v = Wr[(long)i0 * EMBED + k] * (1.0f - lam) + Wr[(long)i1 * EMBED + k] * lam;
        split2(v, g_wrh[j], g_wrl[j]);
    } else if (i < n2 + nr + TTOT) {
        const int t = (int)(i - n2 - nr);
        interp_coef(t, i0, i1, lam);
        g_b2[t] = bs[i0] * (1.0f - lam) + bs[i1] * lam;
    } else {
        const int t = (int)(i - n2 - nr - TTOT);
        interp_coef(t, i0, i1, lam);
        g_br[t] = brs[i0] * (1.0f - lam) + brs[i1] * lam;
    }
}

// ---------------- grouping: pair same-class samples ------------------------
__global__ void group_kernel(const int* __restrict__ psz) {
    if (threadIdx.x != 0) return;
    int slot = 0;
    for (int c = 0; c < 4; c++) {
        int prev = -1;
        for (int i = 0; i < NSAMP; i++) {
            const int ps = psz[i];
            const int cls = (ps == 8) ? 0 : (ps == 16) ? 1 : (ps == 32) ? 2 : 3;
            if (cls != c) continue;
            if (prev < 0) prev = i;
            else { g_pairA[slot] = prev; g_pairB[slot] = i; g_pairCls[slot] = c; slot++; prev = -1; }
        }
        if (prev >= 0) { g_pairA[slot] = prev; g_pairB[slot] = -1; g_pairCls[slot] = c; slot++; }
    }
    for (; slot < MAXPAIRS; slot++) g_pairCls[slot] = -1;
}

// ---------------- zero-fill: out[n, :, T(n):max_dim] = 0 --------------------
__global__ void zerofill_kernel(const int* __restrict__ psz, float* __restrict__ out, int max_dim) {
    const int n = blockIdx.x;
    const int T = psz[n] * OUTD;
    const int w4 = (max_dim - T) >> 2;          // both multiples of 4
    if (w4 <= 0) return;
    float* base = out + (size_t)n * PTOK * max_dim + T;
    const float4 z = make_float4(0.f, 0.f, 0.f, 0.f);
    for (int idx = threadIdx.x; idx < PTOK * w4; idx += blockDim.x) {
        const int r = idx / w4, c = idx % w4;
        *reinterpret_cast<float4*>(base + (size_t)r * max_dim + c * 4) = z;
    }
}

// ---------------- GEMM1: xs = x @ W_in^T + b_in (256x128 tiles) -------------
__global__ void __launch_bounds__(256)
gemm1_kernel(const float* __restrict__ b_in) {
    extern __shared__ char smem[];
    const uint32_t sb = smem_to_u32(smem);
    const int tid = threadIdx.x;
    const int lane = tid & 31, wid = tid >> 5;
    const int warp_m = wid & 3, warp_n = wid >> 2;
    const long bm = (long)blockIdx.y * 256;
    const long bn = (long)blockIdx.x * 128;

    float acc[4][8][4];
#pragma unroll
    for (int i = 0; i < 4; i++)
#pragma unroll
        for (int j = 0; j < 8; j++)
#pragma unroll
            for (int e = 0; e < 4; e++) acc[i][j][e] = 0.0f;

    {
        load_tileA(sb,              g_xh,  bm, EMBED, 0, tid);
        load_tileA(sb + TILE_A,     g_xl,  bm, EMBED, 0, tid);
        load_tileB(sb + 2 * TILE_A,           g_wih, bn, EMBED, 0, tid, 128);
        load_tileB(sb + 2 * TILE_A + TILE_BT, g_wil, bn, EMBED, 0, tid, 128);
        CP_COMMIT();
    }
    const int nK = EMBED / KC;
    for (int ks = 0; ks < nK; ks++) {
        CP_WAIT0();
        __syncthreads();
        if (ks + 1 < nK) {
            const uint32_t base = sb + ((ks + 1) & 1) * STAGE_B;
            const int k0 = (ks + 1) * KC;
            load_tileA(base,              g_xh,  bm, EMBED, k0, tid);
            load_tileA(base + TILE_A,     g_xl,  bm, EMBED, k0, tid);
            load_tileB(base + 2 * TILE_A,           g_wih, bn, EMBED, k0, tid, 128);
            load_tileB(base + 2 * TILE_A + TILE_BT, g_wil, bn, EMBED, k0, tid, 128);
            CP_COMMIT();
        }
        mma_stage(sb + (ks & 1) * STAGE_B, lane, warp_m, warp_n, acc);
    }

    // epilogue: +b_in, split to bf16 hi/lo, store
    const int r0 = lane >> 2;
    const int c0 = (lane & 3) * 2;
#pragma unroll
    for (int i = 0; i < 4; i++) {
        const long rowA = bm + warp_m * 64 + i * 16 + r0;
        const long rowB = rowA + 8;
#pragma unroll
        for (int j = 0; j < 8; j++) {
            const long col = bn + warp_n * 64 + j * 8 + c0;
            const float bi0 = b_in[col], bi1 = b_in[col + 1];
            __nv_bfloat16 h0, l0, h1, l1;
            split2(acc[i][j][0] + bi0, h0, l0);
            split2(acc[i][j][1] + bi1, h1, l1);
            *(uint32_t*)(g_xsh + rowA * INTER + col) = pack2(h0, h1);
            *(uint32_t*)(g_xsl + rowA * INTER + col) = pack2(l0, l1);
            split2(acc[i][j][2] + bi0, h0, l0);
            split2(acc[i][j][3] + bi1, h1, l1);
            *(uint32_t*)(g_xsh + rowB * INTER + col) = pack2(h0, h1);
            *(uint32_t*)(g_xsl + rowB * INTER + col) = pack2(l0, l1);
        }
    }
}

// ---------------- head kernel: pair of same-class samples -------------------
__global__ void __launch_bounds__(256)
head_kernel(float* __restrict__ out, int max_dim) {
    const int slot = blockIdx.y;
    const int cls = g_pairCls[slot];
    if (cls < 0) return;
    const int t0 = blockIdx.x * 128;
    const int T = c_T[cls];
    if (t0 >= T) return;
    const int toff = c_Toff[cls];
    const int s0 = g_pairA[slot];
    const int s1 = g_pairB[slot];
    const bool s1v = (s1 >= 0);

    extern __shared__ char smem[];
    const uint32_t sb = smem_to_u32(smem);
    const int tid = threadIdx.x;
    const int lane = tid & 31, wid = tid >> 5;
    const int warp_m = wid & 3, warp_n = wid >> 2;

    const int tmax = min(T - t0, 128);
    const long a0 = (long)s0 * PTOK;
    const long a1 = s1v ? (long)s1 * PTOK : a0;
    const long brow = (long)toff + t0;

    float acc[4][8][4];
#pragma unroll
    for (int i = 0; i < 4; i++)
#pragma unroll
        for (int j = 0; j < 8; j++)
#pragma unroll
            for (int e = 0; e < 4; e++) acc[i][j][e] = 0.0f;

    const int r0 = lane >> 2;
    const int c0 = (lane & 3) * 2;

    // ---- pass 1: lin = xs @ w2_seg^T  (K = 4096) ----
    {
        load_tileA_pair(sb,          g_xsh, a0, a1, INTER, 0, tid, s1v);
        load_tileA_pair(sb + TILE_A, g_xsl, a0, a1, INTER, 0, tid, s1v);
        load_tileB(sb + 2 * TILE_A,           g_w2h, brow, INTER, 0, tid, tmax);
        load_tileB(sb + 2 * TILE_A + TILE_BT, g_w2l, brow, INTER, 0, tid, tmax);
        CP_COMMIT();
    }
    const int nK1 = INTER / KC;
    for (int ks = 0; ks < nK1; ks++) {
        CP_WAIT0();
        __syncthreads();
        if (ks + 1 < nK1) {
            const uint32_t base = sb + ((ks + 1) & 1) * STAGE_B;
            const int k0 = (ks + 1) * KC;
            load_tileA_pair(base,          g_xsh, a0, a1, INTER, k0, tid, s1v);
            load_tileA_pair(base + TILE_A, g_xsl, a0, a1, INTER, k0, tid, s1v);
            load_tileB(base + 2 * TILE_A,           g_w2h, brow, INTER, k0, tid, tmax);
            load_tileB(base + 2 * TILE_A + TILE_BT, g_w2l, brow, INTER, k0, tid, tmax);
            CP_COMMIT();
        }
        mma_stage(sb + (ks & 1) * STAGE_B, lane, warp_m, warp_n, acc);
    }

    // ---- silu(lin + b2) in registers ----
#pragma unroll
    for (int j = 0; j < 8; j++) {
        const int col = t0 + warp_n * 64 + j * 8 + c0;
        const float b20 = (col     < T) ? g_b2[toff + col]     : 0.0f;
        const float b21 = (col + 1 < T) ? g_b2[toff + col + 1] : 0.0f;
#pragma unroll
        for (int i = 0; i < 4; i++) {
            float v;
            v = acc[i][j][0] + b20; acc[i][j][0] = v / (1.0f + __expf(-v));
            v = acc[i][j][1] + b21; acc[i][j][1] = v / (1.0f + __expf(-v));
            v = acc[i][j][2] + b20; acc[i][j][2] = v / (1.0f + __expf(-v));
            v = acc[i][j][3] + b21; acc[i][j][3] = v / (1.0f + __expf(-v));
        }
    }

    // ---- pass 2: acc += x @ wr_seg^T  (K = 1024) ----
    {
        load_tileA_pair(sb,          g_xh, a0, a1, EMBED, 0, tid, s1v);
        load_tileA_pair(sb + TILE_A, g_xl, a0, a1, EMBED, 0, tid, s1v);
        load_tileB(sb + 2 * TILE_A,           g_wrh, brow, EMBED, 0, tid, tmax);
        load_tileB(sb + 2 * TILE_A + TILE_BT, g_wrl, brow, EMBED, 0, tid, tmax);
        CP_COMMIT();
    }
    const int nK2 = EMBED / KC;
    for (int ks = 0; ks < nK2; ks++) {
        CP_WAIT0();
        __syncthreads();
        if (ks + 1 < nK2) {
            const uint32_t base = sb + ((ks + 1) & 1) * STAGE_B;
            const int k0 = (ks + 1) * KC;
            load_tileA_pair(base,          g_xh, a0, a1, EMBED, k0, tid, s1v);
            load_tileA_pair(base + TILE_A, g_xl, a0, a1, EMBED, k0, tid, s1v);
            load_tileB(base + 2 * TILE_A,           g_wrh, brow, EMBED, k0, tid, tmax);
            load_tileB(base + 2 * TILE_A + TILE_BT, g_wrl, brow, EMBED, k0, tid, tmax);
            CP_COMMIT();
        }
        mma_stage(sb + (ks & 1) * STAGE_B, lane, warp_m, warp_n, acc);
    }

    // ---- store: acc + br for cols < T (zero region handled by zerofill) ----
    const int smp = (warp_m < 2) ? s0 : s1;       // rows 0-127 -> s0, 128-255 -> s1
    if (smp < 0) return;
#pragma unroll
    for (int i = 0; i < 4; i++) {
        const int rbase = (warp_m & 1) * 64 + i * 16 + r0;   // row within sample
        float* orow0 = out + ((size_t)smp * PTOK + rbase) * max_dim;
        float* orow1 = orow0 + (size_t)8 * max_dim;
#pragma unroll
        for (int j = 0; j < 8; j++) {
            const int col = t0 + warp_n * 64 + j * 8 + c0;
            if (col < T) {   // col even, T even -> col+1 < T too
                const float br0 = g_br[toff + col], br1 = g_br[toff + col + 1];
                *reinterpret_cast<float2*>(orow0 + col) =
                    make_float2(acc[i][j][0] + br0, acc[i][j][1] + br1);
                *reinterpret_cast<float2*>(orow1 + col) =
                    make_float2(acc[i][j][2] + br0, acc[i][j][3] + br1);
            }
        }
    }
}

// ----------------------------------------------------------------------------
extern "C" void kernel_launch(void* const* d_in, const int* in_sizes, int n_in,
                              void* d_out, int out_size)
{
    const float* x     = (const float*)d_in[0];
    const int*   psz   = (const int*)d_in[1];
    const float* W_in  = (const float*)d_in[2];
    const float* b_in  = (const float*)d_in[3];
    const float* W_sh  = (const float*)d_in[4];
    const float* b_sh  = (const float*)d_in[5];
    const float* W_res = (const float*)d_in[6];
    const float* b_res = (const float*)d_in[7];
    float* out = (float*)d_out;

    const int max_dim = out_size / (NSAMP * PTOK);

    cudaFuncSetAttribute(gemm1_kernel, cudaFuncAttributeMaxDynamicSharedMemorySize, SMEM_TOTAL);
    cudaFuncSetAttribute(head_kernel,  cudaFuncAttributeMaxDynamicSharedMemorySize, SMEM_TOTAL);

    // 1) split x / W_in into bf16 hi/lo
    {
        const long total = (long)MROWS * EMBED + (long)INTER * EMBED;
        split_inputs_kernel<<<(unsigned)((total + 255) / 256), 256>>>(x, W_in);
    }
    // 2) interpolated head weights (bf16 hi/lo, t-major) + fp32 biases
    {
        const long total = (long)TTOT * INTER + (long)TTOT * EMBED + 2L * TTOT;
        build_weights_kernel<<<(unsigned)((total + 255) / 256), 256>>>(W_sh, b_sh, W_res, b_res);
    }
    // 3) pair table + output zero padding
    group_kernel<<<1, 32>>>(psz);
    zerofill_kernel<<<NSAMP, 256>>>(psz, out, max_dim);
    // 4) xs = x @ W_in^T + b_in
    {
        dim3 g(INTER / 128, MROWS / 256);   // (32, 128)
        gemm1_kernel<<<g, 256, SMEM_TOTAL>>>(b_in);
    }
    // 5) fused per-pair heads
    {
        dim3 g((max_dim + 127) / 128, MAXPAIRS);
        head_kernel<<<g, 256, SMEM_TOTAL>>>(out, max_dim);
    }
}

// round 7
// speedup vs baseline: 1.5057x; 1.5057x over previous
#include <cuda_runtime.h>
#include <cuda_fp16.h>
#include <math.h>
#include <stdint.h>

// ============================================================================
// MultiSizeProjHead via portable mma.sync — fp16 2-term (A single, B hi/lo)
// Weights pre-scaled x256 (keeps B-lo plane in fp16 normal range); epilogues
// multiply by 1/256. R5 structure: 128x128 tiles, 2 CTAs/SM, double buffer.
// ============================================================================
#define EMBED   1024
#define INTER   4096
#define SBASE   672
#define OUTD    21
#define NSAMP   256
#define PTOK    128
#define MROWS   (NSAMP * PTOK)
#define TTOT    2520        // 168 + 336 + 672 + 1344

#define KC       32                  // K per SMEM stage
#define TSTRIDE  80                  // bytes per smem row: 32 fp16 + 8 pad
#define TILE_B   (128 * TSTRIDE)     // 10240 bytes per 128x32 tile
#define STAGE_B  (3 * TILE_B)        // A, Bh, Bl = 30720
#define SMEM_TOTAL (2 * STAGE_B)     // double buffered: 61440 B

#define WSCALE   256.0f
#define INVWS    0.00390625f         // 1/256

__device__ __constant__ int c_T[4]    = {168, 336, 672, 1344};
__device__ __constant__ int c_Toff[4] = {0, 168, 504, 1176};

// ---------------- device scratch (no runtime allocation allowed) -----------
__device__ __half g_xf [(size_t)MROWS * EMBED];     // x, fp16 single plane
__device__ __half g_wih[(size_t)INTER * EMBED];     // W_in*256 hi
__device__ __half g_wil[(size_t)INTER * EMBED];     // W_in*256 lo
__device__ __half g_xsf[(size_t)MROWS * INTER];     // xs, fp16 single plane
__device__ __half g_w2h[(size_t)TTOT * INTER];      // interp W_shared^T *256, t-major
__device__ __half g_w2l[(size_t)TTOT * INTER];
__device__ __half g_wrh[(size_t)TTOT * EMBED];
__device__ __half g_wrl[(size_t)TTOT * EMBED];
__device__ float g_b2[TTOT];
__device__ float g_br[TTOT];

// ---------------- portable PTX helpers -------------------------------------
__device__ __forceinline__ uint32_t smem_to_u32(const void* p) {
    uint32_t a;
    asm("{ .reg .u64 t; cvta.to.shared.u64 t, %1; cvt.u32.u64 %0, t; }" : "=r"(a) : "l"(p));
    return a;
}
__device__ __forceinline__ void cp_async16(uint32_t dst, const void* src, uint32_t src_bytes) {
    asm volatile("cp.async.cg.shared.global [%0], [%1], 16, %2;"
                 :: "r"(dst), "l"(src), "r"(src_bytes) : "memory");
}
#define CP_COMMIT() asm volatile("cp.async.commit_group;" ::: "memory")
#define CP_WAIT0()  asm volatile("cp.async.wait_group 0;" ::: "memory")

__device__ __forceinline__ void ldsm_x4(uint32_t* r, uint32_t addr) {
    asm volatile("ldmatrix.sync.aligned.m8n8.x4.shared.b16 {%0,%1,%2,%3}, [%4];"
                 : "=r"(r[0]), "=r"(r[1]), "=r"(r[2]), "=r"(r[3]) : "r"(addr));
}
__device__ __forceinline__ void mma16816(float* c, const uint32_t* a, uint32_t b0, uint32_t b1) {
    asm volatile("mma.sync.aligned.m16n8k16.row.col.f32.f16.f16.f32 "
                 "{%0,%1,%2,%3}, {%4,%5,%6,%7}, {%8,%9}, {%0,%1,%2,%3};"
                 : "+f"(c[0]), "+f"(c[1]), "+f"(c[2]), "+f"(c[3])
                 : "r"(a[0]), "r"(a[1]), "r"(a[2]), "r"(a[3]), "r"(b0), "r"(b1));
}
// weight split with x256 prescale: v*256 = h + l exactly to ~2^-22
__device__ __forceinline__ void splitw(float v, __half& h, __half& l) {
    const float s = v * WSCALE;
    h = __float2half_rn(s);
    l = __float2half_rn(s - __half2float(h));
}
__device__ __forceinline__ uint32_t pack2h(__half a, __half b) {
    return (uint32_t)__half_as_ushort(a) | ((uint32_t)__half_as_ushort(b) << 16);
}

// async-load one 128x32 fp16 tile (rows padded to 80B); rows >= vrows zero-fill
__device__ __forceinline__ void load_tile_async(uint32_t sdst, const __half* __restrict__ src,
                                                long row0, long stride, int k0, int tid, int vrows) {
#pragma unroll
    for (int i = 0; i < 2; i++) {
        const int c = tid + (i << 8);          // 0..511 chunks of 16B
        const int row = c >> 2, c4 = c & 3;
        const uint32_t d = sdst + (uint32_t)(row * TSTRIDE + c4 * 16);
        const bool ok = (row < vrows);
        const long srow = ok ? (row0 + row) : row0;
        const void* s = src + srow * stride + k0 + c4 * 8;
        cp_async16(d, s, ok ? 16u : 0u);
    }
}

// one KC=32 stage of 2-term MMA: acc += A*Bh + A*Bl   (warp tile 64x32)
__device__ __forceinline__ void mma_stage(uint32_t base, int lane, int warp_m, int warp_n,
                                          float acc[4][4][4]) {
    const int lr = lane & 7, lg = lane >> 3;
    const int rowSel = ((lg & 1) << 3) + lr;
    const int colHalf = (lg >> 1) << 3;
#pragma unroll
    for (int k16 = 0; k16 < KC; k16 += 16) {
        const uint32_t colOff = (uint32_t)((k16 + colHalf) * 2);
        uint32_t a[4][4], bh[2][4], bl[2][4];
#pragma unroll
        for (int i = 0; i < 4; i++) {
            const uint32_t addr = base + (uint32_t)((warp_m * 64 + i * 16 + rowSel) * TSTRIDE) + colOff;
            ldsm_x4(a[i], addr);
        }
#pragma unroll
        for (int jj = 0; jj < 2; jj++) {
            const uint32_t addr = base + TILE_B +
                (uint32_t)((warp_n * 32 + jj * 16 + rowSel) * TSTRIDE) + colOff;
            ldsm_x4(bh[jj], addr);
            ldsm_x4(bl[jj], addr + TILE_B);
        }
#pragma unroll
        for (int i = 0; i < 4; i++)
#pragma unroll
            for (int j = 0; j < 4; j++)
                mma16816(acc[i][j], a[i], bh[j >> 1][j & 1], bh[j >> 1][(j & 1) + 2]);
#pragma unroll
        for (int i = 0; i < 4; i++)
#pragma unroll
            for (int j = 0; j < 4; j++)
                mma16816(acc[i][j], a[i], bl[j >> 1][j & 1], bl[j >> 1][(j & 1) + 2]);
    }
}

// ---------------- prep kernel 1: x -> fp16, W_in -> fp16 hi/lo (x256) ------
__global__ void split_inputs_kernel(const float* __restrict__ x, const float* __restrict__ W_in) {
    const long nx = (long)MROWS * EMBED;
    const long nw = (long)INTER * EMBED;
    const long i = blockIdx.x * (long)blockDim.x + threadIdx.x;
    if (i >= nx + nw) return;
    if (i < nx) {
        g_xf[i] = __float2half_rn(x[i]);
    } else {
        const long j = i - nx;
        splitw(W_in[j], g_wih[j], g_wil[j]);
    }
}

// ---------------- prep kernel 2: interpolated head weights (t-major) -------
__device__ __forceinline__ void interp_coef(int tg, int& i0, int& i1, float& lam) {
    const int s = (tg < 168) ? 0 : (tg < 504) ? 1 : (tg < 1176) ? 2 : 3;
    const int t = tg - c_Toff[s];
    const float scale = (float)SBASE / (float)c_T[s];
    float src = fmaxf(((float)t + 0.5f) * scale - 0.5f, 0.0f);
    i0 = (int)src;                  // src >= 0 -> trunc == floor
    if (i0 > SBASE - 1) i0 = SBASE - 1;
    i1 = min(i0 + 1, SBASE - 1);
    lam = src - (float)i0;
}

__global__ void build_weights_kernel(const float* __restrict__ Ws, const float* __restrict__ bs,
                                     const float* __restrict__ Wr, const float* __restrict__ brs) {
    const long n2 = (long)TTOT * INTER;
    const long nr = (long)TTOT * EMBED;
    const long total = n2 + nr + 2 * TTOT;
    const long i = blockIdx.x * (long)blockDim.x + threadIdx.x;
    if (i >= total) return;
    int i0, i1; float lam;
    if (i < n2) {
        const int t = (int)(i / INTER), k = (int)(i % INTER);
        interp_coef(t, i0, i1, lam);
        const float v = Ws[(long)i0 * INTER + k] * (1.0f - lam) + Ws[(long)i1 * INTER + k] * lam;
        splitw(v, g_w2h[i], g_w2l[i]);
    } else if (i < n2 + nr) {
        const long j = i - n2;
        const int t = (int)(j / EMBED), k = (int)(j % EMBED);
        interp_coef(t, i0, i1, lam);
        const float v = Wr[(long)i0 * EMBED + k] * (1.0f - lam) + Wr[(long)i1 * EMBED + k] * lam;
        splitw(v, g_wrh[j], g_wrl[j]);
    } else if (i < n2 + nr + TTOT) {
        const int t = (int)(i - n2 - nr);
        interp_coef(t, i0, i1, lam);
        g_b2[t] = bs[i0] * (1.0f - lam) + bs[i1] * lam;
    } else {
        const int t = (int)(i - n2 - nr - TTOT);
        interp_coef(t, i0, i1, lam);
        g_br[t] = brs[i0] * (1.0f - lam) + brs[i1] * lam;
    }
}

// ---------------- GEMM1: xs = x @ W_in^T + b_in ------------------------------
__global__ void __launch_bounds__(256)
gemm1_kernel(const float* __restrict__ b_in) {
    extern __shared__ char smem[];
    const uint32_t sb = smem_to_u32(smem);
    const int tid = threadIdx.x;
    const int lane = tid & 31, wid = tid >> 5;
    const int warp_m = wid >> 2, warp_n = wid & 3;
    const long bm = (long)blockIdx.y * 128;
    const long bn = (long)blockIdx.x * 128;

    float acc[4][4][4];
#pragma unroll
    for (int i = 0; i < 4; i++)
#pragma unroll
        for (int j = 0; j < 4; j++)
#pragma unroll
            for (int e = 0; e < 4; e++) acc[i][j][e] = 0.0f;

    {
        load_tile_async(sb,              g_xf,  bm, EMBED, 0, tid, 128);
        load_tile_async(sb + TILE_B,     g_wih, bn, EMBED, 0, tid, 128);
        load_tile_async(sb + 2 * TILE_B, g_wil, bn, EMBED, 0, tid, 128);
        CP_COMMIT();
    }
    const int nK = EMBED / KC;
    for (int ks = 0; ks < nK; ks++) {
        CP_WAIT0();
        __syncthreads();
        if (ks + 1 < nK) {
            const uint32_t base = sb + ((ks + 1) & 1) * STAGE_B;
            const int k0 = (ks + 1) * KC;
            load_tile_async(base,              g_xf,  bm, EMBED, k0, tid, 128);
            load_tile_async(base + TILE_B,     g_wih, bn, EMBED, k0, tid, 128);
            load_tile_async(base + 2 * TILE_B, g_wil, bn, EMBED, k0, tid, 128);
            CP_COMMIT();
        }
        mma_stage(sb + (ks & 1) * STAGE_B, lane, warp_m, warp_n, acc);
    }

    // epilogue: acc/256 + b_in -> fp16 single plane
    const int r0 = lane >> 2;
    const int c0 = (lane & 3) * 2;
#pragma unroll
    for (int i = 0; i < 4; i++) {
        const long rowA = bm + warp_m * 64 + i * 16 + r0;
        const long rowB = rowA + 8;
#pragma unroll
        for (int j = 0; j < 4; j++) {
            const long col = bn + warp_n * 32 + j * 8 + c0;
            const float bi0 = b_in[col], bi1 = b_in[col + 1];
            *(uint32_t*)(g_xsf + rowA * INTER + col) =
                pack2h(__float2half_rn(acc[i][j][0] * INVWS + bi0),
                       __float2half_rn(acc[i][j][1] * INVWS + bi1));
            *(uint32_t*)(g_xsf + rowB * INTER + col) =
                pack2h(__float2half_rn(acc[i][j][2] * INVWS + bi0),
                       __float2half_rn(acc[i][j][3] * INVWS + bi1));
        }
    }
}

// ---------------- head kernel: silu(xs@w2+b2) + x@wr+br + padding ----------
__global__ void __launch_bounds__(256)
head_kernel(const int* __restrict__ psz, float* __restrict__ out, int max_dim) {
    const int n  = blockIdx.y;
    const int t0 = blockIdx.x * 128;
    const int tid = threadIdx.x;

    const int ps = psz[n];
    const int T = ps * OUTD;
    const int s4 = (ps == 8) ? 0 : (ps == 16) ? 1 : (ps == 32) ? 2 : 3;
    const int toff = c_Toff[s4];
    float* outBase = out + (size_t)n * PTOK * max_dim;

    if (t0 >= T) {  // pure zero-pad tile
        const int colq = min(128, max_dim - t0) >> 2;
        const float4 z = make_float4(0.f, 0.f, 0.f, 0.f);
        for (int idx = tid; idx < PTOK * colq; idx += 256) {
            const int r = idx / colq, c = idx % colq;
            *reinterpret_cast<float4*>(outBase + (size_t)r * max_dim + t0 + c * 4) = z;
        }
        return;
    }

    extern __shared__ char smem[];
    const uint32_t sb = smem_to_u32(smem);
    const int lane = tid & 31, wid = tid >> 5;
    const int warp_m = wid >> 2, warp_n = wid & 3;

    const int tmax = min(T - t0, 128);
    const long arow = (long)n * PTOK;
    const long brow = (long)toff + t0;

    float acc[4][4][4];
#pragma unroll
    for (int i = 0; i < 4; i++)
#pragma unroll
        for (int j = 0; j < 4; j++)
#pragma unroll
            for (int e = 0; e < 4; e++) acc[i][j][e] = 0.0f;

    const int r0 = lane >> 2;
    const int c0 = (lane & 3) * 2;

    // ---- pass 1: lin = xs @ w2_seg^T  (K = 4096) ----
    {
        load_tile_async(sb,              g_xsf, arow, INTER, 0, tid, 128);
        load_tile_async(sb + TILE_B,     g_w2h, brow, INTER, 0, tid, tmax);
        load_tile_async(sb + 2 * TILE_B, g_w2l, brow, INTER, 0, tid, tmax);
        CP_COMMIT();
    }
    const int nK1 = INTER / KC;
    for (int ks = 0; ks < nK1; ks++) {
        CP_WAIT0();
        __syncthreads();
        if (ks + 1 < nK1) {
            const uint32_t base = sb + ((ks + 1) & 1) * STAGE_B;
            const int k0 = (ks + 1) * KC;
            load_tile_async(base,              g_xsf, arow, INTER, k0, tid, 128);
            load_tile_async(base + TILE_B,     g_w2h, brow, INTER, k0, tid, tmax);
            load_tile_async(base + 2 * TILE_B, g_w2l, brow, INTER, k0, tid, tmax);
            CP_COMMIT();
        }
        mma_stage(sb + (ks & 1) * STAGE_B, lane, warp_m, warp_n, acc);
    }

    // ---- silu(acc/256 + b2) in registers ----
#pragma unroll
    for (int j = 0; j < 4; j++) {
        const int col = t0 + warp_n * 32 + j * 8 + c0;
        const float b20 = (col     < T) ? g_b2[toff + col]     : 0.0f;
        const float b21 = (col + 1 < T) ? g_b2[toff + col + 1] : 0.0f;
#pragma unroll
        for (int i = 0; i < 4; i++) {
            float v;
            v = acc[i][j][0] * INVWS + b20; acc[i][j][0] = v / (1.0f + __expf(-v));
            v = acc[i][j][1] * INVWS + b21; acc[i][j][1] = v / (1.0f + __expf(-v));
            v = acc[i][j][2] * INVWS + b20; acc[i][j][2] = v / (1.0f + __expf(-v));
            v = acc[i][j][3] * INVWS + b21; acc[i][j][3] = v / (1.0f + __expf(-v));
        }
    }

    // ---- pass 2: res accumulated separately, then acc += res/256 ----
    float acc2[4][4][4];
#pragma unroll
    for (int i = 0; i < 4; i++)
#pragma unroll
        for (int j = 0; j < 4; j++)
#pragma unroll
            for (int e = 0; e < 4; e++) acc2[i][j][e] = 0.0f;
    {
        load_tile_async(sb,              g_xf,  arow, EMBED, 0, tid, 128);
        load_tile_async(sb + TILE_B,     g_wrh, brow, EMBED, 0, tid, tmax);
        load_tile_async(sb + 2 * TILE_B, g_wrl, brow, EMBED, 0, tid, tmax);
        CP_COMMIT();
    }
    const int nK2 = EMBED / KC;
    for (int ks = 0; ks < nK2; ks++) {
        CP_WAIT0();
        __syncthreads();
        if (ks + 1 < nK2) {
            const uint32_t base = sb + ((ks + 1) & 1) * STAGE_B;
            const int k0 = (ks + 1) * KC;
            load_tile_async(base,              g_xf,  arow, EMBED, k0, tid, 128);
            load_tile_async(base + TILE_B,     g_wrh, brow, EMBED, k0, tid, tmax);
            load_tile_async(base + 2 * TILE_B, g_wrl, brow, EMBED, k0, tid, tmax);
            CP_COMMIT();
        }
        mma_stage(sb + (ks & 1) * STAGE_B, lane, warp_m, warp_n, acc2);
    }

    // ---- store: silu + res/256 + br (cols < T), zeros to max_dim ----
#pragma unroll
    for (int i = 0; i < 4; i++) {
        const int rowA = warp_m * 64 + i * 16 + r0;
#pragma unroll
        for (int j = 0; j < 4; j++) {
            const int col = t0 + warp_n * 32 + j * 8 + c0;
            if (col >= max_dim) continue;
            float2 v0, v1;
            if (col < T) {   // T even, col even -> col+1 < T too
                const float br0 = g_br[toff + col], br1 = g_br[toff + col + 1];
                v0 = make_float2(acc[i][j][0] + acc2[i][j][0] * INVWS + br0,
                                 acc[i][j][1] + acc2[i][j][1] * INVWS + br1);
                v1 = make_float2(acc[i][j][2] + acc2[i][j][2] * INVWS + br0,
                                 acc[i][j][3] + acc2[i][j][3] * INVWS + br1);
            } else {
                v0 = make_float2(0.f, 0.f);
                v1 = v0;
            }
            *reinterpret_cast<float2*>(outBase + (size_t)rowA * max_dim + col) = v0;
            *reinterpret_cast<float2*>(outBase + (size_t)(rowA + 8) * max_dim + col) = v1;
        }
    }
}

// ----------------------------------------------------------------------------
extern "C" void kernel_launch(void* const* d_in, const int* in_sizes, int n_in,
                              void* d_out, int out_size)
{
    const float* x     = (const float*)d_in[0];
    const int*   psz   = (const int*)d_in[1];
    const float* W_in  = (const float*)d_in[2];
    const float* b_in  = (const float*)d_in[3];
    const float* W_sh  = (const float*)d_in[4];
    const float* b_sh  = (const float*)d_in[5];
    const float* W_res = (const float*)d_in[6];
    const float* b_res = (const float*)d_in[7];
    float* out = (float*)d_out;

    const int max_dim = out_size / (NSAMP * PTOK);

    cudaFuncSetAttribute(gemm1_kernel, cudaFuncAttributeMaxDynamicSharedMemorySize, SMEM_TOTAL);
    cudaFuncSetAttribute(head_kernel,  cudaFuncAttributeMaxDynamicSharedMemorySize, SMEM_TOTAL);

    // 1) x -> fp16; W_in -> fp16 hi/lo (x256)
    {
        const long total = (long)MROWS * EMBED + (long)INTER * EMBED;
        split_inputs_kernel<<<(unsigned)((total + 255) / 256), 256>>>(x, W_in);
    }
    // 2) interpolated head weights (fp16 hi/lo, x256, t-major) + fp32 biases
    {
        const long total = (long)TTOT * INTER + (long)TTOT * EMBED + 2L * TTOT;
        build_weights_kernel<<<(unsigned)((total + 255) / 256), 256>>>(W_sh, b_sh, W_res, b_res);
    }
    // 3) xs = x @ W_in^T + b_in
    {
        dim3 g(INTER / 128, MROWS / 128);   // (32, 256)
        gemm1_kernel<<<g, 256, SMEM_TOTAL>>>(b_in);
    }
    // 4) fused per-sample heads + zero padding
    {
        dim3 g((max_dim + 127) / 128, NSAMP);
        head_kernel<<<g, 256, SMEM_TOTAL>>>(psz, out, max_dim);
    }
}

// round 8
// speedup vs baseline: 1.6447x; 1.0923x over previous
#include <cuda_runtime.h>
#include <cuda_fp16.h>
#include <math.h>
#include <stdint.h>

// ============================================================================
// MultiSizeProjHead via portable mma.sync — fp16 2-term (A single, B hi/lo)
// R8: single accumulator bank in head kernel (silu rescaled x256 so pass-2
// accumulates in-place), __launch_bounds__(256,2) -> 2 CTAs/SM.
// ============================================================================
#define EMBED   1024
#define INTER   4096
#define SBASE   672
#define OUTD    21
#define NSAMP   256
#define PTOK    128
#define MROWS   (NSAMP * PTOK)
#define TTOT    2520        // 168 + 336 + 672 + 1344

#define KC       32                  // K per SMEM stage
#define TSTRIDE  80                  // bytes per smem row: 32 fp16 + 8 pad
#define TILE_B   (128 * TSTRIDE)     // 10240 bytes per 128x32 tile
#define STAGE_B  (3 * TILE_B)        // A, Bh, Bl = 30720
#define SMEM_TOTAL (2 * STAGE_B)     // double buffered: 61440 B

#define WSCALE   256.0f
#define INVWS    0.00390625f         // 1/256

__device__ __constant__ int c_T[4]    = {168, 336, 672, 1344};
__device__ __constant__ int c_Toff[4] = {0, 168, 504, 1176};

// ---------------- device scratch (no runtime allocation allowed) -----------
__device__ __half g_xf [(size_t)MROWS * EMBED];     // x, fp16 single plane
__device__ __half g_wih[(size_t)INTER * EMBED];     // W_in*256 hi
__device__ __half g_wil[(size_t)INTER * EMBED];     // W_in*256 lo
__device__ __half g_xsf[(size_t)MROWS * INTER];     // xs, fp16 single plane
__device__ __half g_w2h[(size_t)TTOT * INTER];      // interp W_shared^T *256, t-major
__device__ __half g_w2l[(size_t)TTOT * INTER];
__device__ __half g_wrh[(size_t)TTOT * EMBED];
__device__ __half g_wrl[(size_t)TTOT * EMBED];
__device__ float g_b2[TTOT];
__device__ float g_br[TTOT];

// ---------------- portable PTX helpers -------------------------------------
__device__ __forceinline__ uint32_t smem_to_u32(const void* p) {
    uint32_t a;
    asm("{ .reg .u64 t; cvta.to.shared.u64 t, %1; cvt.u32.u64 %0, t; }" : "=r"(a) : "l"(p));
    return a;
}
__device__ __forceinline__ void cp_async16(uint32_t dst, const void* src, uint32_t src_bytes) {
    asm volatile("cp.async.cg.shared.global [%0], [%1], 16, %2;"
                 :: "r"(dst), "l"(src), "r"(src_bytes) : "memory");
}
#define CP_COMMIT() asm volatile("cp.async.commit_group;" ::: "memory")
#define CP_WAIT0()  asm volatile("cp.async.wait_group 0;" ::: "memory")

__device__ __forceinline__ void ldsm_x4(uint32_t* r, uint32_t addr) {
    asm volatile("ldmatrix.sync.aligned.m8n8.x4.shared.b16 {%0,%1,%2,%3}, [%4];"
                 : "=r"(r[0]), "=r"(r[1]), "=r"(r[2]), "=r"(r[3]) : "r"(addr));
}
__device__ __forceinline__ void mma16816(float* c, const uint32_t* a, uint32_t b0, uint32_t b1) {
    asm volatile("mma.sync.aligned.m16n8k16.row.col.f32.f16.f16.f32 "
                 "{%0,%1,%2,%3}, {%4,%5,%6,%7}, {%8,%9}, {%0,%1,%2,%3};"
                 : "+f"(c[0]), "+f"(c[1]), "+f"(c[2]), "+f"(c[3])
                 : "r"(a[0]), "r"(a[1]), "r"(a[2]), "r"(a[3]), "r"(b0), "r"(b1));
}
// weight split with x256 prescale: v*256 = h + l exactly to ~2^-22
__device__ __forceinline__ void splitw(float v, __half& h, __half& l) {
    const float s = v * WSCALE;
    h = __float2half_rn(s);
    l = __float2half_rn(s - __half2float(h));
}
__device__ __forceinline__ uint32_t pack2h(__half a, __half b) {
    return (uint32_t)__half_as_ushort(a) | ((uint32_t)__half_as_ushort(b) << 16);
}

// async-load one 128x32 fp16 tile (rows padded to 80B); rows >= vrows zero-fill
__device__ __forceinline__ void load_tile_async(uint32_t sdst, const __half* __restrict__ src,
                                                long row0, long stride, int k0, int tid, int vrows) {
#pragma unroll
    for (int i = 0; i < 2; i++) {
        const int c = tid + (i << 8);          // 0..511 chunks of 16B
        const int row = c >> 2, c4 = c & 3;
        const uint32_t d = sdst + (uint32_t)(row * TSTRIDE + c4 * 16);
        const bool ok = (row < vrows);
        const long srow = ok ? (row0 + row) : row0;
        const void* s = src + srow * stride + k0 + c4 * 8;
        cp_async16(d, s, ok ? 16u : 0u);
    }
}

// one KC=32 stage of 2-term MMA: acc += A*Bh + A*Bl   (warp tile 64x32)
__device__ __forceinline__ void mma_stage(uint32_t base, int lane, int warp_m, int warp_n,
                                          float acc[4][4][4]) {
    const int lr = lane & 7, lg = lane >> 3;
    const int rowSel = ((lg & 1) << 3) + lr;
    const int colHalf = (lg >> 1) << 3;
#pragma unroll
    for (int k16 = 0; k16 < KC; k16 += 16) {
        const uint32_t colOff = (uint32_t)((k16 + colHalf) * 2);
        uint32_t a[4][4], bh[2][4], bl[2][4];
#pragma unroll
        for (int i = 0; i < 4; i++) {
            const uint32_t addr = base + (uint32_t)((warp_m * 64 + i * 16 + rowSel) * TSTRIDE) + colOff;
            ldsm_x4(a[i], addr);
        }
#pragma unroll
        for (int jj = 0; jj < 2; jj++) {
            const uint32_t addr = base + TILE_B +
                (uint32_t)((warp_n * 32 + jj * 16 + rowSel) * TSTRIDE) + colOff;
            ldsm_x4(bh[jj], addr);
            ldsm_x4(bl[jj], addr + TILE_B);
        }
#pragma unroll
        for (int i = 0; i < 4; i++)
#pragma unroll
            for (int j = 0; j < 4; j++)
                mma16816(acc[i][j], a[i], bh[j >> 1][j & 1], bh[j >> 1][(j & 1) + 2]);
#pragma unroll
        for (int i = 0; i < 4; i++)
#pragma unroll
            for (int j = 0; j < 4; j++)
                mma16816(acc[i][j], a[i], bl[j >> 1][j & 1], bl[j >> 1][(j & 1) + 2]);
    }
}

// ---------------- prep kernel 1: x -> fp16, W_in -> fp16 hi/lo (x256) ------
__global__ void split_inputs_kernel(const float* __restrict__ x, const float* __restrict__ W_in) {
    const long nx = (long)MROWS * EMBED;
    const long nw = (long)INTER * EMBED;
    const long i = blockIdx.x * (long)blockDim.x + threadIdx.x;
    if (i >= nx + nw) return;
    if (i < nx) {
        g_xf[i] = __float2half_rn(x[i]);
    } else {
        const long j = i - nx;
        splitw(W_in[j], g_wih[j], g_wil[j]);
    }
}

// ---------------- prep kernel 2: interpolated head weights (t-major) -------
__device__ __forceinline__ void interp_coef(int tg, int& i0, int& i1, float& lam) {
    const int s = (tg < 168) ? 0 : (tg < 504) ? 1 : (tg < 1176) ? 2 : 3;
    const int t = tg - c_Toff[s];
    const float scale = (float)SBASE / (float)c_T[s];
    float src = fmaxf(((float)t + 0.5f) * scale - 0.5f, 0.0f);
    i0 = (int)src;                  // src >= 0 -> trunc == floor
    if (i0 > SBASE - 1) i0 = SBASE - 1;
    i1 = min(i0 + 1, SBASE - 1);
    lam = src - (float)i0;
}

__global__ void build_weights_kernel(const float* __restrict__ Ws, const float* __restrict__ bs,
                                     const float* __restrict__ Wr, const float* __restrict__ brs) {
    const long n2 = (long)TTOT * INTER;
    const long nr = (long)TTOT * EMBED;
    const long total = n2 + nr + 2 * TTOT;
    const long i = blockIdx.x * (long)blockDim.x + threadIdx.x;
    if (i >= total) return;
    int i0, i1; float lam;
    if (i < n2) {
        const int t = (int)(i / INTER), k = (int)(i % INTER);
        interp_coef(t, i0, i1, lam);
        const float v = Ws[(long)i0 * INTER + k] * (1.0f - lam) + Ws[(long)i1 * INTER + k] * lam;
        splitw(v, g_w2h[i], g_w2l[i]);
    } else if (i < n2 + nr) {
        const long j = i - n2;
        const int t = (int)(j / EMBED), k = (int)(j % EMBED);
        interp_coef(t, i0, i1, lam);
        const float v = Wr[(long)i0 * EMBED + k] * (1.0f - lam) + Wr[(long)i1 * EMBED + k] * lam;
        splitw(v, g_wrh[j], g_wrl[j]);
    } else if (i < n2 + nr + TTOT) {
        const int t = (int)(i - n2 - nr);
        interp_coef(t, i0, i1, lam);
        g_b2[t] = bs[i0] * (1.0f - lam) + bs[i1] * lam;
    } else {
        const int t = (int)(i - n2 - nr - TTOT);
        interp_coef(t, i0, i1, lam);
        g_br[t] = brs[i0] * (1.0f - lam) + brs[i1] * lam;
    }
}

// ---------------- GEMM1: xs = x @ W_in^T + b_in ------------------------------
__global__ void __launch_bounds__(256, 2)
gemm1_kernel(const float* __restrict__ b_in) {
    extern __shared__ char smem[];
    const uint32_t sb = smem_to_u32(smem);
    const int tid = threadIdx.x;
    const int lane = tid & 31, wid = tid >> 5;
    const int warp_m = wid >> 2, warp_n = wid & 3;
    const long bm = (long)blockIdx.y * 128;
    const long bn = (long)blockIdx.x * 128;

    float acc[4][4][4];
#pragma unroll
    for (int i = 0; i < 4; i++)
#pragma unroll
        for (int j = 0; j < 4; j++)
#pragma unroll
            for (int e = 0; e < 4; e++) acc[i][j][e] = 0.0f;

    {
        load_tile_async(sb,              g_xf,  bm, EMBED, 0, tid, 128);
        load_tile_async(sb + TILE_B,     g_wih, bn, EMBED, 0, tid, 128);
        load_tile_async(sb + 2 * TILE_B, g_wil, bn, EMBED, 0, tid, 128);
        CP_COMMIT();
    }
    const int nK = EMBED / KC;
    for (int ks = 0; ks < nK; ks++) {
        CP_WAIT0();
        __syncthreads();
        if (ks + 1 < nK) {
            const uint32_t base = sb + ((ks + 1) & 1) * STAGE_B;
            const int k0 = (ks + 1) * KC;
            load_tile_async(base,              g_xf,  bm, EMBED, k0, tid, 128);
            load_tile_async(base + TILE_B,     g_wih, bn, EMBED, k0, tid, 128);
            load_tile_async(base + 2 * TILE_B, g_wil, bn, EMBED, k0, tid, 128);
            CP_COMMIT();
        }
        mma_stage(sb + (ks & 1) * STAGE_B, lane, warp_m, warp_n, acc);
    }

    // epilogue: acc/256 + b_in -> fp16 single plane
    const int r0 = lane >> 2;
    const int c0 = (lane & 3) * 2;
#pragma unroll
    for (int i = 0; i < 4; i++) {
        const long rowA = bm + warp_m * 64 + i * 16 + r0;
        const long rowB = rowA + 8;
#pragma unroll
        for (int j = 0; j < 4; j++) {
            const long col = bn + warp_n * 32 + j * 8 + c0;
            const float bi0 = b_in[col], bi1 = b_in[col + 1];
            *(uint32_t*)(g_xsf + rowA * INTER + col) =
                pack2h(__float2half_rn(acc[i][j][0] * INVWS + bi0),
                       __float2half_rn(acc[i][j][1] * INVWS + bi1));
            *(uint32_t*)(g_xsf + rowB * INTER + col) =
                pack2h(__float2half_rn(acc[i][j][2] * INVWS + bi0),
                       __float2half_rn(acc[i][j][3] * INVWS + bi1));
        }
    }
}

// ---------------- head kernel: silu(xs@w2+b2) + x@wr+br + padding ----------
// Single accumulator bank: after pass-1 silu, values are rescaled x256 so the
// pass-2 MMAs (weights pre-scaled x256) accumulate in place; store does /256.
__global__ void __launch_bounds__(256, 2)
head_kernel(const int* __restrict__ psz, float* __restrict__ out, int max_dim) {
    const int n  = blockIdx.y;
    const int t0 = blockIdx.x * 128;
    const int tid = threadIdx.x;

    const int ps = psz[n];
    const int T = ps * OUTD;
    const int s4 = (ps == 8) ? 0 : (ps == 16) ? 1 : (ps == 32) ? 2 : 3;
    const int toff = c_Toff[s4];
    float* outBase = out + (size_t)n * PTOK * max_dim;

    if (t0 >= T) {  // pure zero-pad tile
        const int colq = min(128, max_dim - t0) >> 2;
        const float4 z = make_float4(0.f, 0.f, 0.f, 0.f);
        for (int idx = tid; idx < PTOK * colq; idx += 256) {
            const int r = idx / colq, c = idx % colq;
            *reinterpret_cast<float4*>(outBase + (size_t)r * max_dim + t0 + c * 4) = z;
        }
        return;
    }

    extern __shared__ char smem[];
    const uint32_t sb = smem_to_u32(smem);
    const int lane = tid & 31, wid = tid >> 5;
    const int warp_m = wid >> 2, warp_n = wid & 3;

    const int tmax = min(T - t0, 128);
    const long arow = (long)n * PTOK;
    const long brow = (long)toff + t0;

    float acc[4][4][4];
#pragma unroll
    for (int i = 0; i < 4; i++)
#pragma unroll
        for (int j = 0; j < 4; j++)
#pragma unroll
            for (int e = 0; e < 4; e++) acc[i][j][e] = 0.0f;

    const int r0 = lane >> 2;
    const int c0 = (lane & 3) * 2;

    // ---- pass 1: lin = xs @ w2_seg^T  (K = 4096) ----
    {
        load_tile_async(sb,              g_xsf, arow, INTER, 0, tid, 128);
        load_tile_async(sb + TILE_B,     g_w2h, brow, INTER, 0, tid, tmax);
        load_tile_async(sb + 2 * TILE_B, g_w2l, brow, INTER, 0, tid, tmax);
        CP_COMMIT();
    }
    const int nK1 = INTER / KC;
    for (int ks = 0; ks < nK1; ks++) {
        CP_WAIT0();
        __syncthreads();
        if (ks + 1 < nK1) {
            const uint32_t base = sb + ((ks + 1) & 1) * STAGE_B;
            const int k0 = (ks + 1) * KC;
            load_tile_async(base,              g_xsf, arow, INTER, k0, tid, 128);
            load_tile_async(base + TILE_B,     g_w2h, brow, INTER, k0, tid, tmax);
            load_tile_async(base + 2 * TILE_B, g_w2l, brow, INTER, k0, tid, tmax);
            CP_COMMIT();
        }
        mma_stage(sb + (ks & 1) * STAGE_B, lane, warp_m, warp_n, acc);
    }

    // ---- silu(acc/256 + b2), rescaled x256 so pass 2 can accumulate in place
#pragma unroll
    for (int j = 0; j < 4; j++) {
        const int col = t0 + warp_n * 32 + j * 8 + c0;
        const float b20 = (col     < T) ? g_b2[toff + col]     : 0.0f;
        const float b21 = (col + 1 < T) ? g_b2[toff + col + 1] : 0.0f;
#pragma unroll
        for (int i = 0; i < 4; i++) {
            float v;
            v = acc[i][j][0] * INVWS + b20; acc[i][j][0] = v / (1.0f + __expf(-v)) * WSCALE;
            v = acc[i][j][1] * INVWS + b21; acc[i][j][1] = v / (1.0f + __expf(-v)) * WSCALE;
            v = acc[i][j][2] * INVWS + b20; acc[i][j][2] = v / (1.0f + __expf(-v)) * WSCALE;
            v = acc[i][j][3] * INVWS + b21; acc[i][j][3] = v / (1.0f + __expf(-v)) * WSCALE;
        }
    }

    // ---- pass 2: acc += x @ (wr*256)_seg^T  (K = 1024), same registers ----
    {
        load_tile_async(sb,              g_xf,  arow, EMBED, 0, tid, 128);
        load_tile_async(sb + TILE_B,     g_wrh, brow, EMBED, 0, tid, tmax);
        load_tile_async(sb + 2 * TILE_B, g_wrl, brow, EMBED, 0, tid, tmax);
        CP_COMMIT();
    }
    const int nK2 = EMBED / KC;
    for (int ks = 0; ks < nK2; ks++) {
        CP_WAIT0();
        __syncthreads();
        if (ks + 1 < nK2) {
            const uint32_t base = sb + ((ks + 1) & 1) * STAGE_B;
            const int k0 = (ks + 1) * KC;
            load_tile_async(base,              g_xf,  arow, EMBED, k0, tid, 128);
            load_tile_async(base + TILE_B,     g_wrh, brow, EMBED, k0, tid, tmax);
            load_tile_async(base + 2 * TILE_B, g_wrl, brow, EMBED, k0, tid, tmax);
            CP_COMMIT();
        }
        mma_stage(sb + (ks & 1) * STAGE_B, lane, warp_m, warp_n, acc);
    }

    // ---- store: acc/256 + br (cols < T), zeros to max_dim ----
#pragma unroll
    for (int i = 0; i < 4; i++) {
        const int rowA = warp_m * 64 + i * 16 + r0;
#pragma unroll
        for (int j = 0; j < 4; j++) {
            const int col = t0 + warp_n * 32 + j * 8 + c0;
            if (col >= max_dim) continue;
            float2 v0, v1;
            if (col < T) {   // T even, col even -> col+1 < T too
                const float br0 = g_br[toff + col], br1 = g_br[toff + col + 1];
                v0 = make_float2(acc[i][j][0] * INVWS + br0, acc[i][j][1] * INVWS + br1);
                v1 = make_float2(acc[i][j][2] * INVWS + br0, acc[i][j][3] * INVWS + br1);
            } else {
                v0 = make_float2(0.f, 0.f);
                v1 = v0;
            }
            *reinterpret_cast<float2*>(outBase + (size_t)rowA * max_dim + col) = v0;
            *reinterpret_cast<float2*>(outBase + (size_t)(rowA + 8) * max_dim + col) = v1;
        }
    }
}

// ----------------------------------------------------------------------------
extern "C" void kernel_launch(void* const* d_in, const int* in_sizes, int n_in,
                              void* d_out, int out_size)
{
    const float* x     = (const float*)d_in[0];
    const int*   psz   = (const int*)d_in[1];
    const float* W_in  = (const float*)d_in[2];
    const float* b_in  = (const float*)d_in[3];
    const float* W_sh  = (const float*)d_in[4];
    const float* b_sh  = (const float*)d_in[5];
    const float* W_res = (const float*)d_in[6];
    const float* b_res = (const float*)d_in[7];
    float* out = (float*)d_out;

    const int max_dim = out_size / (NSAMP * PTOK);

    cudaFuncSetAttribute(gemm1_kernel, cudaFuncAttributeMaxDynamicSharedMemorySize, SMEM_TOTAL);
    cudaFuncSetAttribute(head_kernel,  cudaFuncAttributeMaxDynamicSharedMemorySize, SMEM_TOTAL);

    // 1) x -> fp16; W_in -> fp16 hi/lo (x256)
    {
        const long total = (long)MROWS * EMBED + (long)INTER * EMBED;
        split_inputs_kernel<<<(unsigned)((total + 255) / 256), 256>>>(x, W_in);
    }
    // 2) interpolated head weights (fp16 hi/lo, x256, t-major) + fp32 biases
    {
        const long total = (long)TTOT * INTER + (long)TTOT * EMBED + 2L * TTOT;
        build_weights_kernel<<<(unsigned)((total + 255) / 256), 256>>>(W_sh, b_sh, W_res, b_res);
    }
    // 3) xs = x @ W_in^T + b_in
    {
        dim3 g(INTER / 128, MROWS / 128);   // (32, 256)
        gemm1_kernel<<<g, 256, SMEM_TOTAL>>>(b_in);
    }
    // 4) fused per-sample heads + zero padding
    {
        dim3 g((max_dim + 127) / 128, NSAMP);
        head_kernel<<<g, 256, SMEM_TOTAL>>>(psz, out, max_dim);
    }
}

// round 9
// speedup vs baseline: 2.9875x; 1.8164x over previous
#include <cuda_runtime.h>
#include <cuda_fp16.h>
#include <math.h>
#include <stdint.h>

// ============================================================================
// MultiSizeProjHead via portable mma.sync — single-plane fp16 x fp16 (1 term)
// Weights pre-scaled x256 (exact, keeps small values normal); epilogues /256.
// KC=64 stages, double-buffered cp.async, 128x128 tiles, 2 CTAs/SM.
// ============================================================================
#define EMBED   1024
#define INTER   4096
#define SBASE   672
#define OUTD    21
#define NSAMP   256
#define PTOK    128
#define MROWS   (NSAMP * PTOK)
#define TTOT    2520        // 168 + 336 + 672 + 1344

#define KC       64                  // K per SMEM stage
#define TSTRIDE  144                 // bytes per smem row: 64 fp16 + 16 pad
#define TILE_B   (128 * TSTRIDE)     // 18432 bytes per 128x64 tile
#define STAGE_B  (2 * TILE_B)        // A, B = 36864
#define SMEM_TOTAL (2 * STAGE_B)     // double buffered: 73728 B

#define WSCALE   256.0f
#define INVWS    0.00390625f         // 1/256

__device__ __constant__ int c_T[4]    = {168, 336, 672, 1344};
__device__ __constant__ int c_Toff[4] = {0, 168, 504, 1176};

// ---------------- device scratch (no runtime allocation allowed) -----------
__device__ __half g_xf [(size_t)MROWS * EMBED];     // x, fp16
__device__ __half g_wi [(size_t)INTER * EMBED];     // W_in*256, fp16
__device__ __half g_xsf[(size_t)MROWS * INTER];     // xs, fp16
__device__ __half g_w2 [(size_t)TTOT * INTER];      // interp W_shared^T *256, t-major
__device__ __half g_wr [(size_t)TTOT * EMBED];      // interp W_res^T *256, t-major
__device__ float g_b2[TTOT];
__device__ float g_br[TTOT];

// ---------------- portable PTX helpers -------------------------------------
__device__ __forceinline__ uint32_t smem_to_u32(const void* p) {
    uint32_t a;
    asm("{ .reg .u64 t; cvta.to.shared.u64 t, %1; cvt.u32.u64 %0, t; }" : "=r"(a) : "l"(p));
    return a;
}
__device__ __forceinline__ void cp_async16(uint32_t dst, const void* src, uint32_t src_bytes) {
    asm volatile("cp.async.cg.shared.global [%0], [%1], 16, %2;"
                 :: "r"(dst), "l"(src), "r"(src_bytes) : "memory");
}
#define CP_COMMIT() asm volatile("cp.async.commit_group;" ::: "memory")
#define CP_WAIT0()  asm volatile("cp.async.wait_group 0;" ::: "memory")

__device__ __forceinline__ void ldsm_x4(uint32_t* r, uint32_t addr) {
    asm volatile("ldmatrix.sync.aligned.m8n8.x4.shared.b16 {%0,%1,%2,%3}, [%4];"
                 : "=r"(r[0]), "=r"(r[1]), "=r"(r[2]), "=r"(r[3]) : "r"(addr));
}
__device__ __forceinline__ void mma16816(float* c, const uint32_t* a, uint32_t b0, uint32_t b1) {
    asm volatile("mma.sync.aligned.m16n8k16.row.col.f32.f16.f16.f32 "
                 "{%0,%1,%2,%3}, {%4,%5,%6,%7}, {%8,%9}, {%0,%1,%2,%3};"
                 : "+f"(c[0]), "+f"(c[1]), "+f"(c[2]), "+f"(c[3])
                 : "r"(a[0]), "r"(a[1]), "r"(a[2]), "r"(a[3]), "r"(b0), "r"(b1));
}
__device__ __forceinline__ uint32_t pack2h(__half a, __half b) {
    return (uint32_t)__half_as_ushort(a) | ((uint32_t)__half_as_ushort(b) << 16);
}

// async-load one 128x64 fp16 tile (rows padded to 144B); rows >= vrows zero-fill
__device__ __forceinline__ void load_tile_async(uint32_t sdst, const __half* __restrict__ src,
                                                long row0, long stride, int k0, int tid, int vrows) {
#pragma unroll
    for (int i = 0; i < 4; i++) {
        const int c = tid + (i << 8);          // 0..1023 chunks of 16B
        const int row = c >> 3, c8 = c & 7;
        const uint32_t d = sdst + (uint32_t)(row * TSTRIDE + c8 * 16);
        const bool ok = (row < vrows);
        const long srow = ok ? (row0 + row) : row0;
        const void* s = src + srow * stride + k0 + c8 * 8;
        cp_async16(d, s, ok ? 16u : 0u);
    }
}

// one KC=64 stage of 1-term MMA: acc += A*B   (warp tile 64x32)
__device__ __forceinline__ void mma_stage(uint32_t base, int lane, int warp_m, int warp_n,
                                          float acc[4][4][4]) {
    const int lr = lane & 7, lg = lane >> 3;
    const int rowSel = ((lg & 1) << 3) + lr;
    const int colHalf = (lg >> 1) << 3;
#pragma unroll
    for (int k16 = 0; k16 < KC; k16 += 16) {
        const uint32_t colOff = (uint32_t)((k16 + colHalf) * 2);
        uint32_t a[4][4], b[2][4];
#pragma unroll
        for (int i = 0; i < 4; i++) {
            const uint32_t addr = base + (uint32_t)((warp_m * 64 + i * 16 + rowSel) * TSTRIDE) + colOff;
            ldsm_x4(a[i], addr);
        }
#pragma unroll
        for (int jj = 0; jj < 2; jj++) {
            const uint32_t addr = base + TILE_B +
                (uint32_t)((warp_n * 32 + jj * 16 + rowSel) * TSTRIDE) + colOff;
            ldsm_x4(b[jj], addr);
        }
#pragma unroll
        for (int i = 0; i < 4; i++)
#pragma unroll
            for (int j = 0; j < 4; j++)
                mma16816(acc[i][j], a[i], b[j >> 1][j & 1], b[j >> 1][(j & 1) + 2]);
    }
}

// ---------------- prep kernel 1: x -> fp16, W_in -> fp16 (x256) ------------
__global__ void split_inputs_kernel(const float* __restrict__ x, const float* __restrict__ W_in) {
    const long nx = (long)MROWS * EMBED;
    const long nw = (long)INTER * EMBED;
    const long i = blockIdx.x * (long)blockDim.x + threadIdx.x;
    if (i >= nx + nw) return;
    if (i < nx) {
        g_xf[i] = __float2half_rn(x[i]);
    } else {
        const long j = i - nx;
        g_wi[j] = __float2half_rn(W_in[j] * WSCALE);
    }
}

// ---------------- prep kernel 2: interpolated head weights (t-major) -------
__device__ __forceinline__ void interp_coef(int tg, int& i0, int& i1, float& lam) {
    const int s = (tg < 168) ? 0 : (tg < 504) ? 1 : (tg < 1176) ? 2 : 3;
    const int t = tg - c_Toff[s];
    const float scale = (float)SBASE / (float)c_T[s];
    float src = fmaxf(((float)t + 0.5f) * scale - 0.5f, 0.0f);
    i0 = (int)src;                  // src >= 0 -> trunc == floor
    if (i0 > SBASE - 1) i0 = SBASE - 1;
    i1 = min(i0 + 1, SBASE - 1);
    lam = src - (float)i0;
}

__global__ void build_weights_kernel(const float* __restrict__ Ws, const float* __restrict__ bs,
                                     const float* __restrict__ Wr, const float* __restrict__ brs) {
    const long n2 = (long)TTOT * INTER;
    const long nr = (long)TTOT * EMBED;
    const long total = n2 + nr + 2 * TTOT;
    const long i = blockIdx.x * (long)blockDim.x + threadIdx.x;
    if (i >= total) return;
    int i0, i1; float lam;
    if (i < n2) {
        const int t = (int)(i / INTER), k = (int)(i % INTER);
        interp_coef(t, i0, i1, lam);
        const float v = Ws[(long)i0 * INTER + k] * (1.0f - lam) + Ws[(long)i1 * INTER + k] * lam;
        g_w2[i] = __float2half_rn(v * WSCALE);
    } else if (i < n2 + nr) {
        const long j = i - n2;
        const int t = (int)(j / EMBED), k = (int)(j % EMBED);
        interp_coef(t, i0, i1, lam);
        const float v = Wr[(long)i0 * EMBED + k] * (1.0f - lam) + Wr[(long)i1 * EMBED + k] * lam;
        g_wr[j] = __float2half_rn(v * WSCALE);
    } else if (i < n2 + nr + TTOT) {
        const int t = (int)(i - n2 - nr);
        interp_coef(t, i0, i1, lam);
        g_b2[t] = bs[i0] * (1.0f - lam) + bs[i1] * lam;
    } else {
        const int t = (int)(i - n2 - nr - TTOT);
        interp_coef(t, i0, i1, lam);
        g_br[t] = brs[i0] * (1.0f - lam) + brs[i1] * lam;
    }
}

// ---------------- GEMM1: xs = x @ W_in^T + b_in ------------------------------
__global__ void __launch_bounds__(256, 2)
gemm1_kernel(const float* __restrict__ b_in) {
    extern __shared__ char smem[];
    const uint32_t sb = smem_to_u32(smem);
    const int tid = threadIdx.x;
    const int lane = tid & 31, wid = tid >> 5;
    const int warp_m = wid >> 2, warp_n = wid & 3;
    const long bm = (long)blockIdx.y * 128;
    const long bn = (long)blockIdx.x * 128;

    float acc[4][4][4];
#pragma unroll
    for (int i = 0; i < 4; i++)
#pragma unroll
        for (int j = 0; j < 4; j++)
#pragma unroll
            for (int e = 0; e < 4; e++) acc[i][j][e] = 0.0f;

    {
        load_tile_async(sb,          g_xf, bm, EMBED, 0, tid, 128);
        load_tile_async(sb + TILE_B, g_wi, bn, EMBED, 0, tid, 128);
        CP_COMMIT();
    }
    const int nK = EMBED / KC;
    for (int ks = 0; ks < nK; ks++) {
        CP_WAIT0();
        __syncthreads();
        if (ks + 1 < nK) {
            const uint32_t base = sb + ((ks + 1) & 1) * STAGE_B;
            const int k0 = (ks + 1) * KC;
            load_tile_async(base,          g_xf, bm, EMBED, k0, tid, 128);
            load_tile_async(base + TILE_B, g_wi, bn, EMBED, k0, tid, 128);
            CP_COMMIT();
        }
        mma_stage(sb + (ks & 1) * STAGE_B, lane, warp_m, warp_n, acc);
    }

    // epilogue: acc/256 + b_in -> fp16 single plane
    const int r0 = lane >> 2;
    const int c0 = (lane & 3) * 2;
#pragma unroll
    for (int i = 0; i < 4; i++) {
        const long rowA = bm + warp_m * 64 + i * 16 + r0;
        const long rowB = rowA + 8;
#pragma unroll
        for (int j = 0; j < 4; j++) {
            const long col = bn + warp_n * 32 + j * 8 + c0;
            const float bi0 = b_in[col], bi1 = b_in[col + 1];
            *(uint32_t*)(g_xsf + rowA * INTER + col) =
                pack2h(__float2half_rn(acc[i][j][0] * INVWS + bi0),
                       __float2half_rn(acc[i][j][1] * INVWS + bi1));
            *(uint32_t*)(g_xsf + rowB * INTER + col) =
                pack2h(__float2half_rn(acc[i][j][2] * INVWS + bi0),
                       __float2half_rn(acc[i][j][3] * INVWS + bi1));
        }
    }
}

// ---------------- head kernel: silu(xs@w2+b2) + x@wr+br + padding ----------
// Single accumulator bank: silu output rescaled x256 so pass-2 (weights x256)
// accumulates in place; store multiplies by 1/256.
__global__ void __launch_bounds__(256, 2)
head_kernel(const int* __restrict__ psz, float* __restrict__ out, int max_dim) {
    const int n  = blockIdx.y;
    const int t0 = blockIdx.x * 128;
    const int tid = threadIdx.x;

    const int ps = psz[n];
    const int T = ps * OUTD;
    const int s4 = (ps == 8) ? 0 : (ps == 16) ? 1 : (ps == 32) ? 2 : 3;
    const int toff = c_Toff[s4];
    float* outBase = out + (size_t)n * PTOK * max_dim;

    if (t0 >= T) {  // pure zero-pad tile
        const int colq = min(128, max_dim - t0) >> 2;
        const float4 z = make_float4(0.f, 0.f, 0.f, 0.f);
        for (int idx = tid; idx < PTOK * colq; idx += 256) {
            const int r = idx / colq, c = idx % colq;
            *reinterpret_cast<float4*>(outBase + (size_t)r * max_dim + t0 + c * 4) = z;
        }
        return;
    }

    extern __shared__ char smem[];
    const uint32_t sb = smem_to_u32(smem);
    const int lane = tid & 31, wid = tid >> 5;
    const int warp_m = wid >> 2, warp_n = wid & 3;

    const int tmax = min(T - t0, 128);
    const long arow = (long)n * PTOK;
    const long brow = (long)toff + t0;

    float acc[4][4][4];
#pragma unroll
    for (int i = 0; i < 4; i++)
#pragma unroll
        for (int j = 0; j < 4; j++)
#pragma unroll
            for (int e = 0; e < 4; e++) acc[i][j][e] = 0.0f;

    const int r0 = lane >> 2;
    const int c0 = (lane & 3) * 2;

    // ---- pass 1: lin = xs @ w2_seg^T  (K = 4096) ----
    {
        load_tile_async(sb,          g_xsf, arow, INTER, 0, tid, 128);
        load_tile_async(sb + TILE_B, g_w2,  brow, INTER, 0, tid, tmax);
        CP_COMMIT();
    }
    const int nK1 = INTER / KC;
    for (int ks = 0; ks < nK1; ks++) {
        CP_WAIT0();
        __syncthreads();
        if (ks + 1 < nK1) {
            const uint32_t base = sb + ((ks + 1) & 1) * STAGE_B;
            const int k0 = (ks + 1) * KC;
            load_tile_async(base,          g_xsf, arow, INTER, k0, tid, 128);
            load_tile_async(base + TILE_B, g_w2,  brow, INTER, k0, tid, tmax);
            CP_COMMIT();
        }
        mma_stage(sb + (ks & 1) * STAGE_B, lane, warp_m, warp_n, acc);
    }

    // ---- silu(acc/256 + b2), rescaled x256 so pass 2 accumulates in place --
#pragma unroll
    for (int j = 0; j < 4; j++) {
        const int col = t0 + warp_n * 32 + j * 8 + c0;
        const float b20 = (col     < T) ? g_b2[toff + col]     : 0.0f;
        const float b21 = (col + 1 < T) ? g_b2[toff + col + 1] : 0.0f;
#pragma unroll
        for (int i = 0; i < 4; i++) {
            float v;
            v = acc[i][j][0] * INVWS + b20; acc[i][j][0] = v / (1.0f + __expf(-v)) * WSCALE;
            v = acc[i][j][1] * INVWS + b21; acc[i][j][1] = v / (1.0f + __expf(-v)) * WSCALE;
            v = acc[i][j][2] * INVWS + b20; acc[i][j][2] = v / (1.0f + __expf(-v)) * WSCALE;
            v = acc[i][j][3] * INVWS + b21; acc[i][j][3] = v / (1.0f + __expf(-v)) * WSCALE;
        }
    }

    // ---- pass 2: acc += x @ (wr*256)_seg^T  (K = 1024), same registers ----
    {
        load_tile_async(sb,          g_xf, arow, EMBED, 0, tid, 128);
        load_tile_async(sb + TILE_B, g_wr, brow, EMBED, 0, tid, tmax);
        CP_COMMIT();
    }
    const int nK2 = EMBED / KC;
    for (int ks = 0; ks < nK2; ks++) {
        CP_WAIT0();
        __syncthreads();
        if (ks + 1 < nK2) {
            const uint32_t base = sb + ((ks + 1) & 1) * STAGE_B;
            const int k0 = (ks + 1) * KC;
            load_tile_async(base,          g_xf, arow, EMBED, k0, tid, 128);
            load_tile_async(base + TILE_B, g_wr, brow, EMBED, k0, tid, tmax);
            CP_COMMIT();
        }
        mma_stage(sb + (ks & 1) * STAGE_B, lane, warp_m, warp_n, acc);
    }

    // ---- store: acc/256 + br (cols < T), zeros to max_dim ----
#pragma unroll
    for (int i = 0; i < 4; i++) {
        const int rowA = warp_m * 64 + i * 16 + r0;
#pragma unroll
        for (int j = 0; j < 4; j++) {
            const int col = t0 + warp_n * 32 + j * 8 + c0;
            if (col >= max_dim) continue;
            float2 v0, v1;
            if (col < T) {   // T even, col even -> col+1 < T too
                const float br0 = g_br[toff + col], br1 = g_br[toff + col + 1];
                v0 = make_float2(acc[i][j][0] * INVWS + br0, acc[i][j][1] * INVWS + br1);
                v1 = make_float2(acc[i][j][2] * INVWS + br0, acc[i][j][3] * INVWS + br1);
            } else {
                v0 = make_float2(0.f, 0.f);
                v1 = v0;
            }
            *reinterpret_cast<float2*>(outBase + (size_t)rowA * max_dim + col) = v0;
            *reinterpret_cast<float2*>(outBase + (size_t)(rowA + 8) * max_dim + col) = v1;
        }
    }
}

// ----------------------------------------------------------------------------
extern "C" void kernel_launch(void* const* d_in, const int* in_sizes, int n_in,
                              void* d_out, int out_size)
{
    const float* x     = (const float*)d_in[0];
    const int*   psz   = (const int*)d_in[1];
    const float* W_in  = (const float*)d_in[2];
    const float* b_in  = (const float*)d_in[3];
    const float* W_sh  = (const float*)d_in[4];
    const float* b_sh  = (const float*)d_in[5];
    const float* W_res = (const float*)d_in[6];
    const float* b_res = (const float*)d_in[7];
    float* out = (float*)d_out;

    const int max_dim = out_size / (NSAMP * PTOK);

    cudaFuncSetAttribute(gemm1_kernel, cudaFuncAttributeMaxDynamicSharedMemorySize, SMEM_TOTAL);
    cudaFuncSetAttribute(head_kernel,  cudaFuncAttributeMaxDynamicSharedMemorySize, SMEM_TOTAL);

    // 1) x -> fp16; W_in -> fp16 (x256)
    {
        const long total = (long)MROWS * EMBED + (long)INTER * EMBED;
        split_inputs_kernel<<<(unsigned)((total + 255) / 256), 256>>>(x, W_in);
    }
    // 2) interpolated head weights (fp16, x256, t-major) + fp32 biases
    {
        const long total = (long)TTOT * INTER + (long)TTOT * EMBED + 2L * TTOT;
        build_weights_kernel<<<(unsigned)((total + 255) / 256), 256>>>(W_sh, b_sh, W_res, b_res);
    }
    // 3) xs = x @ W_in^T + b_in
    {
        dim3 g(INTER / 128, MROWS / 128);   // (32, 256)
        gemm1_kernel<<<g, 256, SMEM_TOTAL>>>(b_in);
    }
    // 4) fused per-sample heads + zero padding
    {
        dim3 g((max_dim + 127) / 128, NSAMP);
        head_kernel<<<g, 256, SMEM_TOTAL>>>(psz, out, max_dim);
    }
}